// round 6
// baseline (speedup 1.0000x reference)
#include <cuda_runtime.h>
#include <cuda_bf16.h>
#include <cuda_fp8.h>
#include <math.h>
#include <stdint.h>

#define D        512
#define KK       32
#define PP       528
#define MROWS    128
#define KCH      64
#define NCHUNK   9
#define NTHREADS 512

#define H_STRIDE 592
#define Z_STRIDE 1040
#define V_STRIDE 80
#define U_STRIDE 80
#define VCHUNK_BYTES (256 * V_STRIDE)   // 20480
#define VCHUNK_U4    1280

#define SM_GID   0
#define SM_KERN  512
#define SM_PBUF  1024
#define SM_CHG   3072
#define SM_ZMU   5120
#define SM_LUT   7168
#define SM_COORD 8256
#define SM_R2    25216
#define SM_R1    86656
#define SM_TOTAL 219776

__device__ float g_change[D];
__device__ float g_zmu[D];
__device__ float g_xcU[KK];
__device__ float g_dU[KK];
__device__ __align__(16) unsigned short g_iup[544];
__device__ __align__(16) unsigned char g_Ubf[512 * U_STRIDE];
__device__ __align__(16) unsigned char g_V8[18 * VCHUNK_BYTES];

__device__ __forceinline__ uint32_t smem_u32(const void* p) {
    uint32_t a;
    asm("{ .reg .u64 t; cvta.to.shared.u64 t, %1; cvt.u32.u64 %0, t; }" : "=r"(a) : "l"(p));
    return a;
}
__device__ __forceinline__ void ldsm4(uint32_t* r, uint32_t a) {
    asm volatile("ldmatrix.sync.aligned.m8n8.x4.shared.b16 {%0,%1,%2,%3}, [%4];"
                 : "=r"(r[0]), "=r"(r[1]), "=r"(r[2]), "=r"(r[3]) : "r"(a));
}
__device__ __forceinline__ void ldsm4t(uint32_t* r, uint32_t a) {
    asm volatile("ldmatrix.sync.aligned.m8n8.x4.trans.shared.b16 {%0,%1,%2,%3}, [%4];"
                 : "=r"(r[0]), "=r"(r[1]), "=r"(r[2]), "=r"(r[3]) : "r"(a));
}
__device__ __forceinline__ void mma16816(float* c, const uint32_t* a, const uint32_t* b) {
    asm volatile("mma.sync.aligned.m16n8k16.row.col.f32.bf16.bf16.f32 "
                 "{%0,%1,%2,%3}, {%4,%5,%6,%7}, {%8,%9}, {%0,%1,%2,%3};"
                 : "+f"(c[0]), "+f"(c[1]), "+f"(c[2]), "+f"(c[3])
                 : "r"(a[0]), "r"(a[1]), "r"(a[2]), "r"(a[3]), "r"(b[0]), "r"(b[1]));
}
__device__ __forceinline__ void mma8(float* c, const uint32_t* a, uint32_t b0, uint32_t b1) {
    asm volatile("mma.sync.aligned.m16n8k32.row.col.f32.e4m3.e4m3.f32 "
                 "{%0,%1,%2,%3}, {%4,%5,%6,%7}, {%8,%9}, {%0,%1,%2,%3};"
                 : "+f"(c[0]), "+f"(c[1]), "+f"(c[2]), "+f"(c[3])
                 : "r"(a[0]), "r"(a[1]), "r"(a[2]), "r"(a[3]), "r"(b0), "r"(b1));
}
__device__ __forceinline__ uint32_t pack4_e4m3(float f0, float f1, float f2, float f3) {
    uint32_t r;
    asm("{\n\t.reg .b16 lo, hi;\n\t"
        "cvt.rn.satfinite.e4m3x2.f32 lo, %2, %1;\n\t"
        "cvt.rn.satfinite.e4m3x2.f32 hi, %4, %3;\n\t"
        "mov.b32 %0, {lo, hi};\n\t}"
        : "=r"(r) : "f"(f0), "f"(f1), "f"(f2), "f"(f3));
    return r;
}
__device__ __forceinline__ void cp16(uint32_t saddr, const void* g) {
    asm volatile("cp.async.cg.shared.global [%0], [%1], 16;" :: "r"(saddr), "l"(g));
}
__device__ __forceinline__ void cp_commit() {
    asm volatile("cp.async.commit_group;" ::: "memory");
}
template <int N>
__device__ __forceinline__ void cp_wait() {
    asm volatile("cp.async.wait_group %0;" :: "n"(N) : "memory");
}

__global__ void prep_kernel(const float* __restrict__ U,
                            const float* __restrict__ V,
                            const float* __restrict__ zmu,
                            const float* __restrict__ xc) {
    int b = blockIdx.x, t = threadIdx.x;
    if (b < 288) {
        int g = b * 256 + t;
        int chunk = g >> 12;
        int rem = g & 4095;
        int n = rem >> 4;
        int k4 = (rem & 15) << 2;
        int np = chunk / NCHUNK, c = chunk - np * NCHUNK;
        int gk = c * KCH + k4;
        int gn = np * 256 + n;
        float4 v = make_float4(0.f, 0.f, 0.f, 0.f);
        if (gk < PP) v = *(const float4*)(V + (size_t)gn * PP + gk);
        uint32_t w = pack4_e4m3(v.x * 256.f, v.y * 256.f, v.z * 256.f, v.w * 256.f);
        *(uint32_t*)(g_V8 + (size_t)chunk * VCHUNK_BYTES + n * V_STRIDE + k4) = w;
        return;
    }
    if (b < 368) {
        int e = (b - 288) * 256 + t;
        int k = e / 40, n = e - k * 40;
        float v = (n < KK) ? U[k * KK + n] : 0.f;
        *(__nv_bfloat16*)(g_Ubf + k * U_STRIDE + n * 2) = __float2bfloat16(v);
        return;
    }
    __shared__ float pa[256], pb[256], sdiff[KK];
    {
        int j = t & 31, seg = t >> 5;
        float a = 0.f, bb = 0.f;
        for (int i = 0; i < 64; ++i) {
            int d = seg * 64 + i;
            float u = U[d * KK + j];
            a = fmaf(zmu[d], u, a);
            bb = fmaf(xc[d], u, bb);
        }
        pa[t] = a; pb[t] = bb;
    }
    __syncthreads();
    if (t < KK) {
        float sa = 0.f, sb = 0.f;
        for (int s = 0; s < 8; ++s) { sa += pa[s * 32 + t]; sb += pb[s * 32 + t]; }
        g_xcU[t] = sb;
        g_dU[t]  = sb - sa;
        sdiff[t] = sb - sa;
    }
    __syncthreads();
    for (int d = t; d < D; d += 256) {
        float s = 0.f;
        for (int j = 0; j < KK; ++j) s = fmaf(sdiff[j], U[d * KK + j], s);
        g_change[d] = xc[d] - zmu[d] - s;
        g_zmu[d] = zmu[d];
    }
    if (t == 0) {
        int p = 0;
        for (int i = 0; i < KK; ++i)
            for (int j = i; j < KK; ++j) {
                g_iup[p] = (unsigned short)(i | (j << 8));
                ++p;
            }
        for (; p < 544; ++p) g_iup[p] = 0;
    }
}

__global__ __launch_bounds__(NTHREADS, 1)
void glayer_main(const float* __restrict__ Z_all,
                 const int*   __restrict__ choice,
                 float*       __restrict__ out,
                 int Nc) {
    extern __shared__ __align__(16) char sm[];
    const uint32_t smb = smem_u32(sm);

    int*   gid    = (int*)(sm + SM_GID);
    float* kern   = (float*)(sm + SM_KERN);
    float* pbuf   = (float*)(sm + SM_PBUF);
    float* chg    = (float*)(sm + SM_CHG);
    float* zmus   = (float*)(sm + SM_ZMU);
    float* coords = (float*)(sm + SM_COORD);

    const int tid = threadIdx.x;
    const int wid = tid >> 5;
    const int lid = tid & 31;

    if (tid < MROWS) {
        int n = blockIdx.x * MROWS + tid;
        gid[tid] = (n < Nc) ? choice[n] : -1;
    }
    chg[tid]  = g_change[tid];
    zmus[tid] = g_zmu[tid];
    if (tid < 136) ((uint2*)(sm + SM_LUT))[tid] = ((const uint2*)g_iup)[tid];
    {
        const uint4* s = (const uint4*)g_Ubf;
        uint4* d = (uint4*)(sm + SM_R2);
        #pragma unroll
        for (int i = 0; i < 5; ++i) d[tid + i * 512] = s[tid + i * 512];
    }
    __syncthreads();

    // ---- gather Z -> bf16 Zbf + zn partials (4 thr/row) ----
    {
        int r = tid >> 2, q4 = tid & 3;
        int g = gid[r];
        const float4* zr = (const float4*)(Z_all + (size_t)(g < 0 ? 0 : g) * D) + q4 * 32;
        char* zrow = sm + SM_R1 + r * Z_STRIDE + q4 * 256;
        float acc = 0.f;
        #pragma unroll 8
        for (int i = 0; i < 32; ++i) {
            float4 z = make_float4(0.f, 0.f, 0.f, 0.f);
            if (g >= 0) z = zr[i];
            int d0 = q4 * 128 + i * 4;
            float a0 = z.x - zmus[d0], a1 = z.y - zmus[d0 + 1];
            float a2 = z.z - zmus[d0 + 2], a3 = z.w - zmus[d0 + 3];
            acc = fmaf(a0, a0, fmaf(a1, a1, fmaf(a2, a2, fmaf(a3, a3, acc))));
            __nv_bfloat162 p0 = __floats2bfloat162_rn(z.x, z.y);
            __nv_bfloat162 p1 = __floats2bfloat162_rn(z.z, z.w);
            *(uint32_t*)(zrow + i * 8)     = *(uint32_t*)&p0;
            *(uint32_t*)(zrow + i * 8 + 4) = *(uint32_t*)&p1;
        }
        pbuf[tid] = acc;
    }
    __syncthreads();

    // ---- ZU via bf16 mma: 16 warps, each 16 rows x 16 cols ----
    {
        const int nh = (wid >> 3) * 16;
        float zu[2][4];
        #pragma unroll
        for (int i = 0; i < 2; ++i)
            #pragma unroll
            for (int j = 0; j < 4; ++j) zu[i][j] = 0.f;

        uint32_t zbase = smb + SM_R1 + (uint32_t)((wid & 7) * 16 + (lid & 15)) * Z_STRIDE;
        uint32_t ubase = smb + SM_R2 +
                         (uint32_t)((lid & 7) + 8 * ((lid >> 3) & 1)) * U_STRIDE +
                         (uint32_t)(nh + 8 * (lid >> 4)) * 2;
        uint32_t kh = (uint32_t)(8 * (lid >> 4)) * 2;
        #pragma unroll 4
        for (int ks = 0; ks < 32; ++ks) {
            uint32_t a[4], b[4];
            ldsm4(a, zbase + (uint32_t)(ks * 32) + kh);
            ldsm4t(b, ubase + (uint32_t)(ks * 16) * U_STRIDE);
            mma16816(zu[0], a, b);
            mma16816(zu[1], a, b + 2);
        }
        int r0 = (wid & 7) * 16 + (lid >> 2);
        int c0 = (lid & 3) * 2;
        #pragma unroll
        for (int nt = 0; nt < 2; ++nt) {
            int c = nh + nt * 8 + c0;
            coords[r0 * 33 + c]           = zu[nt][0] - g_xcU[c];
            coords[r0 * 33 + c + 1]       = zu[nt][1] - g_xcU[c + 1];
            coords[(r0 + 8) * 33 + c]     = zu[nt][2] - g_xcU[c];
            coords[(r0 + 8) * 33 + c + 1] = zu[nt][3] - g_xcU[c + 1];
        }
    }
    __syncthreads();

    // ---- issue V chunk 0 copy (overlaps secant + H build) ----
    {
        const char* src = (const char*)g_V8;
        #pragma unroll
        for (int i = 0; i < 3; ++i) {
            int idx = tid + i * 512;
            if (idx < VCHUNK_U4) cp16(smb + SM_R2 + idx * 16, src + (size_t)idx * 16);
        }
        cp_commit();
    }

    // ---- secant (threads 0..127) ----
    if (tid < MROWS) {
        const float* cr = coords + tid * 33;
        float un = 0.f;
        #pragma unroll
        for (int j = 0; j < KK; ++j) {
            float v = cr[j] + g_dU[j];
            un = fmaf(v, v, un);
        }
        float zn = pbuf[4 * tid] + pbuf[4 * tid + 1] + pbuf[4 * tid + 2] + pbuf[4 * tid + 3];
        float C = zn - un;
        float E = __expf(-0.01f * un);
        float x_m2 = C * 0.999f;
        float x_m1 = C;
        bool done = false;
        for (int it = 0; it < 100; ++it) {
            if (done) break;
            float t1 = 1.f - E * __expf(-0.01f * x_m1);
            float f1 = t1 * t1 * x_m1 - C;
            float t2 = 1.f - E * __expf(-0.01f * x_m2);
            float f2 = t2 * t2 * x_m2 - C;
            float fd = f1 - f2;
            if (fabsf(fd) < 1e-6f) fd = (fd >= 0.f) ? 1e-6f : -1e-6f;
            float x = x_m1 - f1 * (x_m1 - x_m2) / fd;
            float step = fabsf(x - x_m1);
            x_m2 = x_m1;
            x_m1 = x;
            done = (step < 1e-6f);
        }
        kern[tid] = __expf(-0.01f * (un + x_m1));
    }

    // ---- build H[128][576] fp8 (overwrites Zbf), 4 thr/row ----
    {
        int m = tid >> 2, seg = tid & 3;
        const float* cr = coords + m * 33;
        char* hrow = sm + SM_R1 + m * H_STRIDE;
        const unsigned short* lut = (const unsigned short*)(sm + SM_LUT);
        int p0 = seg * 144, p1 = p0 + 144;
        for (int p = p0; p < p1; p += 4) {
            uint32_t w = 0;
            if (p < PP) {
                uint2 lu = *(const uint2*)(lut + p);
                int a0 = lu.x & 255, b0 = (lu.x >> 8) & 255;
                int a1 = (lu.x >> 16) & 255, b1 = (lu.x >> 24) & 255;
                int a2 = lu.y & 255, b2 = (lu.y >> 8) & 255;
                int a3 = (lu.y >> 16) & 255, b3 = (lu.y >> 24) & 255;
                w = pack4_e4m3(cr[a0] * cr[b0], cr[a1] * cr[b1],
                               cr[a2] * cr[b2], cr[a3] * cr[b3]);
            }
            *(uint32_t*)(hrow + p) = w;
        }
    }

    // ---- main GEMM: 18 flat chunks (2 passes x 9), 3-stage cp.async ----
    const int mg = (wid >> 2) * 32;
    const int ng = (wid & 3) * 64;
    const uint32_t hlane = smb + SM_R1 + (uint32_t)(mg + (lid & 15)) * H_STRIDE +
                           (uint32_t)((lid >> 4) * 16);
    const uint32_t vlane = (uint32_t)(ng + (lid & 7) + 8 * ((lid >> 4) & 1)) * V_STRIDE +
                           (uint32_t)(((lid >> 3) & 1) * 16);
    const float INV256 = 0.00390625f;

    float acc[2][8][4];
    #pragma unroll
    for (int i = 0; i < 2; ++i)
        #pragma unroll
        for (int j = 0; j < 8; ++j)
            #pragma unroll
            for (int q = 0; q < 4; ++q) acc[i][j][q] = 0.f;

    for (int t = 0; t < 18; ++t) {
        if (t + 1 < 18) {
            const char* src = (const char*)(g_V8 + (size_t)(t + 1) * VCHUNK_BYTES);
            uint32_t dstb = smb + SM_R2 + (uint32_t)(((t + 1) % 3) * VCHUNK_BYTES);
            #pragma unroll
            for (int i = 0; i < 3; ++i) {
                int idx = tid + i * 512;
                if (idx < VCHUNK_U4) cp16(dstb + idx * 16, src + (size_t)idx * 16);
            }
            cp_commit();
            cp_wait<1>();
        } else {
            cp_wait<0>();
        }
        __syncthreads();

        const int c = (t >= NCHUNK) ? t - NCHUNK : t;
        const uint32_t vb = smb + SM_R2 + (uint32_t)((t % 3) * VCHUNK_BYTES) + vlane;
        #pragma unroll
        for (int ks = 0; ks < 2; ++ks) {
            uint32_t a[2][4];
            uint32_t koff = (uint32_t)(c * KCH + ks * 32);
            ldsm4(a[0], hlane + koff);
            ldsm4(a[1], hlane + (uint32_t)(16 * H_STRIDE) + koff);
            #pragma unroll
            for (int q = 0; q < 4; ++q) {
                uint32_t bfrag[4];
                ldsm4(bfrag, vb + (uint32_t)(q * 16) * V_STRIDE + (uint32_t)(ks * 32));
                mma8(acc[0][2 * q],     a[0], bfrag[0], bfrag[1]);
                mma8(acc[0][2 * q + 1], a[0], bfrag[2], bfrag[3]);
                mma8(acc[1][2 * q],     a[1], bfrag[0], bfrag[1]);
                mma8(acc[1][2 * q + 1], a[1], bfrag[2], bfrag[3]);
            }
        }

        if (t == NCHUNK - 1 || t == 17) {
            const int np = (t == NCHUNK - 1) ? 0 : 1;
            int r0 = mg + (lid >> 2);
            int c0 = np * 256 + ng + (lid & 3) * 2;
            #pragma unroll
            for (int mt = 0; mt < 2; ++mt) {
                int rA = r0 + mt * 16, rB = rA + 8;
                int gA = gid[rA], gB = gid[rB];
                float kA = kern[rA], kB = kern[rB];
                #pragma unroll
                for (int nt = 0; nt < 8; ++nt) {
                    int col = c0 + nt * 8;
                    float ca = chg[col], cb = chg[col + 1];
                    if (gA >= 0) {
                        float2 z = *(const float2*)(Z_all + (size_t)gA * D + col);
                        float2 o;
                        o.x = z.x + kA * (ca + acc[mt][nt][0] * INV256);
                        o.y = z.y + kA * (cb + acc[mt][nt][1] * INV256);
                        *(float2*)(out + (size_t)gA * D + col) = o;
                    }
                    if (gB >= 0) {
                        float2 z = *(const float2*)(Z_all + (size_t)gB * D + col);
                        float2 o;
                        o.x = z.x + kB * (ca + acc[mt][nt][2] * INV256);
                        o.y = z.y + kB * (cb + acc[mt][nt][3] * INV256);
                        *(float2*)(out + (size_t)gB * D + col) = o;
                    }
                    if (np == 0) {
                        acc[mt][nt][0] = 0.f; acc[mt][nt][1] = 0.f;
                        acc[mt][nt][2] = 0.f; acc[mt][nt][3] = 0.f;
                    }
                }
            }
        }
    }
}

extern "C" void kernel_launch(void* const* d_in, const int* in_sizes, int n_in,
                              void* d_out, int out_size) {
    const float* Z_all  = (const float*)d_in[0];
    const float* U      = (const float*)d_in[1];
    const float* V      = (const float*)d_in[2];
    const float* zmu    = (const float*)d_in[3];
    const float* xc     = (const float*)d_in[4];
    const int*   choice = (const int*)  d_in[5];
    float*       out    = (float*)d_out;
    const int Nc = in_sizes[5];

    if ((size_t)Nc * D != (size_t)in_sizes[0]) {
        cudaMemcpyAsync(d_out, Z_all, (size_t)in_sizes[0] * sizeof(float),
                        cudaMemcpyDeviceToDevice, 0);
    }

    prep_kernel<<<369, 256>>>(U, V, zmu, xc);

    cudaFuncSetAttribute(glayer_main,
                         cudaFuncAttributeMaxDynamicSharedMemorySize, SM_TOTAL);
    int nblocks = (Nc + MROWS - 1) / MROWS;
    glayer_main<<<nblocks, NTHREADS, SM_TOTAL>>>(Z_all, choice, out, Nc);
}